// round 12
// baseline (speedup 1.0000x reference)
#include <cuda_runtime.h>
#include <cuda_bf16.h>
#include <math.h>

// ---------------------------------------------------------------------------
// ConvNet: conv(3->16,5x5) -> hermite -> pool2 -> conv(16->16,5x5) -> hermite
//          -> pool2 -> FC(2704->10).  B=512, input 3x64x64.
// Round 11: pack-free fma.rn.f32x2 (R10 with the macro-arity bug fixed:
// KYS takes row-name prefixes and token-pastes operand names).
//   - inputs in smem as u64 pairs, stored twice: even-aligned (A) and
//     shifted-by-one (B) -> every (kx) operand pair is ONE aligned LDS.64
//   - weights pre-duplicated (w,w) u64, broadcast LDS.64
//   - thread tile: 4 co x 2 conv rows x 4 conv cols (16 u64 accumulators)
// ---------------------------------------------------------------------------

#define B_IMG 512

__device__ float g_pool1[B_IMG * 16 * 30 * 30];   // after conv1+herm+pool
__device__ float g_pool2[B_IMG * 16 * 13 * 13];   // after conv2+herm+pool

typedef unsigned long long u64;

__device__ __forceinline__ u64 pk2(float lo, float hi) {
    u64 r;
    asm("mov.b64 %0, {%1, %2};" : "=l"(r) : "f"(lo), "f"(hi));
    return r;
}
__device__ __forceinline__ void fma2(u64& acc, u64 a, u64 b) {
    asm("fma.rn.f32x2 %0, %1, %2, %0;" : "+l"(acc) : "l"(a), "l"(b));
}
__device__ __forceinline__ float2 upk(u64 v) {
    float2 f;
    asm("mov.b64 {%0, %1}, %2;" : "=f"(f.x), "=f"(f.y) : "l"(v));
    return f;
}

__device__ __forceinline__ float herm4(float x, float a0, float a1, float a2,
                                       float a3, float a4) {
    return fmaf(fmaf(fmaf(fmaf(a4, x, a3), x, a2), x, a1), x, a0);
}

// Load one input row's 7 operand pairs. PTR = u64* at (row base + 2*pcp).
// A pairs at [0..3], B (shifted) pairs at [BOFF..BOFF+2].
#define LOADR(P, PTR, BOFF)                                                 \
    P##a0 = (PTR)[0]; P##a1 = (PTR)[1]; P##a2 = (PTR)[2]; P##a3 = (PTR)[3]; \
    P##b0 = (PTR)[(BOFF)]; P##b1 = (PTR)[(BOFF) + 1]; P##b2 = (PTR)[(BOFF) + 2];

// One ky step: 4 co, 2 output rows. T = row-prefix for output row 0's tap
// row (oy+KY), U = row-prefix for output row 1's tap row (oy+KY+1).
// COSTR = co stride in s_w (u64 units).
#define KYS(KY, COSTR, T, U)                                                \
    _Pragma("unroll")                                                       \
    for (int co_ = 0; co_ < 4; co_++) {                                     \
        const u64* wp_ = wB + co_ * (COSTR) + (KY) * 5;                     \
        u64 w0_ = wp_[0], w1_ = wp_[1], w2_ = wp_[2], w3_ = wp_[3],         \
            w4_ = wp_[4];                                                   \
        fma2(acc[co_][0][0], T##a0, w0_); fma2(acc[co_][0][1], T##a1, w0_); \
        fma2(acc[co_][1][0], U##a0, w0_); fma2(acc[co_][1][1], U##a1, w0_); \
        fma2(acc[co_][0][0], T##b0, w1_); fma2(acc[co_][0][1], T##b1, w1_); \
        fma2(acc[co_][1][0], U##b0, w1_); fma2(acc[co_][1][1], U##b1, w1_); \
        fma2(acc[co_][0][0], T##a1, w2_); fma2(acc[co_][0][1], T##a2, w2_); \
        fma2(acc[co_][1][0], U##a1, w2_); fma2(acc[co_][1][1], U##a2, w2_); \
        fma2(acc[co_][0][0], T##b1, w3_); fma2(acc[co_][0][1], T##b2, w3_); \
        fma2(acc[co_][1][0], U##b1, w3_); fma2(acc[co_][1][1], U##b2, w3_); \
        fma2(acc[co_][0][0], T##a2, w4_); fma2(acc[co_][0][1], T##a3, w4_); \
        fma2(acc[co_][1][0], U##a2, w4_); fma2(acc[co_][1][1], U##a3, w4_); \
    }

// ---------------------------------------------------------------------------
// Kernel 1: conv1 + bias + hermite + maxpool2
// Grid: 512 imgs * 5 bands (6 pooled rows). 384 thr = 4 co-groups x 96
// (90 active: 6 pooled rows x 15 pooled-col-pairs).
// Smem (u64): pairs 3*16*64 = 3072 (24KB), wdup 16*3*25 = 1200 (9.6KB).
// ---------------------------------------------------------------------------
__global__ void __launch_bounds__(384, 2)
conv1_fused_kernel(const float* __restrict__ x,
                   const float* __restrict__ coef,
                   const float* __restrict__ w,
                   const float* __restrict__ bias) {
    extern __shared__ __align__(16) char smem_raw[];
    u64* s_p = (u64*)smem_raw;          // [ch][row][64]: A 0..31, B 32..63
    u64* s_w = s_p + 3072;              // [co][cin][ky][kx] strides 75/25/5/1

    const int img  = blockIdx.x / 5;
    const int band = blockIdx.x % 5;
    const int tid  = threadIdx.x;       // 384

    const float* xim = x + (size_t)img * 3 * 64 * 64;
    const int row0 = band * 12;
    // fill input pairs
    for (int i = tid; i < 3072; i += 384) {
        int c    = i >> 10;             // /1024
        int rem  = i & 1023;
        int row  = rem >> 6;
        int slot = rem & 63;
        const float* gr = xim + c * 4096 + (row0 + row) * 64;
        u64 v;
        if (slot < 32) {                // A: cols (2p, 2p+1)
            int p = slot;
            v = pk2(gr[2 * p], gr[2 * p + 1]);
        } else {                        // B: cols (2p+1, 2p+2)
            int p = slot - 32;
            float hi = (p < 31) ? gr[2 * p + 2] : 0.0f;
            v = pk2(gr[2 * p + 1], hi);
        }
        s_p[i] = v;
    }
    // fill duplicated weights
    for (int i = tid; i < 1200; i += 384) {
        float wv = w[i];
        s_w[i] = pk2(wv, wv);           // same index layout as gmem
    }
    __syncthreads();

    const int g = tid / 96;             // co-group: channels [4g, 4g+4)
    const int t = tid % 96;

    if (t < 90) {
        const int pr  = t / 15;         // pooled row in band 0..5
        const int pcp = t % 15;         // pooled col PAIR 0..14 (2 pooled cols)
        const int oy  = 2 * pr;         // conv row
        const int co0 = 4 * g;
        const int base = oy * 64 + 2 * pcp;

        u64 acc[4][2][2];               // [co][conv row][col pair]
        #pragma unroll
        for (int co = 0; co < 4; co++) {
            float bv = __ldg(bias + co0 + co);
            u64 bb = pk2(bv, bv);
            acc[co][0][0] = bb; acc[co][0][1] = bb;
            acc[co][1][0] = bb; acc[co][1][1] = bb;
        }

        const u64* rp = s_p + base;
        const u64* wB = s_w + co0 * 75;
        #pragma unroll 1
        for (int cin = 0; cin < 3; cin++) {
            u64 Xa0, Xa1, Xa2, Xa3, Xb0, Xb1, Xb2;
            u64 Ya0, Ya1, Ya2, Ya3, Yb0, Yb1, Yb2;
            LOADR(X, rp, 32)            // row oy
            LOADR(Y, rp + 64, 32)       // row oy+1
            KYS(0, 75, X, Y)
            LOADR(X, rp + 128, 32)      // row oy+2
            KYS(1, 75, Y, X)
            LOADR(Y, rp + 192, 32)      // row oy+3
            KYS(2, 75, X, Y)
            LOADR(X, rp + 256, 32)      // row oy+4
            KYS(3, 75, Y, X)
            LOADR(Y, rp + 320, 32)      // row oy+5
            KYS(4, 75, X, Y)
            rp += 1024;
            wB += 25;
        }

        const float c0 = __ldg(coef + 0), c1 = __ldg(coef + 1),
                    c2 = __ldg(coef + 2), c3 = __ldg(coef + 3),
                    c4 = __ldg(coef + 4);
        const float a0 = c0 - 2.0f * c2 + 12.0f * c4;
        const float a1 = 2.0f * c1 - 12.0f * c3;
        const float a2 = 4.0f * c2 - 48.0f * c4;
        const float a3 = 8.0f * c3;
        const float a4 = 16.0f * c4;

        const int py = band * 6 + pr;
        #pragma unroll
        for (int co = 0; co < 4; co++) {
            float2 r0j0 = upk(acc[co][0][0]), r0j1 = upk(acc[co][0][1]);
            float2 r1j0 = upk(acc[co][1][0]), r1j1 = upk(acc[co][1][1]);
            float m0 = fmaxf(fmaxf(herm4(r0j0.x, a0, a1, a2, a3, a4),
                                   herm4(r0j0.y, a0, a1, a2, a3, a4)),
                             fmaxf(herm4(r1j0.x, a0, a1, a2, a3, a4),
                                   herm4(r1j0.y, a0, a1, a2, a3, a4)));
            float m1 = fmaxf(fmaxf(herm4(r0j1.x, a0, a1, a2, a3, a4),
                                   herm4(r0j1.y, a0, a1, a2, a3, a4)),
                             fmaxf(herm4(r1j1.x, a0, a1, a2, a3, a4),
                                   herm4(r1j1.y, a0, a1, a2, a3, a4)));
            int idx = ((img * 16 + co0 + co) * 30 + py) * 30 + 2 * pcp;
            *(float2*)&g_pool1[idx] = make_float2(m0, m1);   // 8B aligned
        }
    }
}

// ---------------------------------------------------------------------------
// Kernel 2: conv2 + bias + hermite + maxpool2
// Grid: 512 (one image). 384 thr = 4 co-groups x 96 (91 active:
// 13 pooled rows x 7 pooled-col-pairs, last pair col-masked).
// Smem (u64): pairs 16*30*32 = 15360 (120KB; rows padded to 32 cols with 0),
//             wdup 16*16*25 = 6400 (51.2KB).  Total ~170KB -> 1 CTA/SM.
// ---------------------------------------------------------------------------
__global__ void __launch_bounds__(384)
conv2_fused_kernel(const float* __restrict__ coef,
                   const float* __restrict__ w,
                   const float* __restrict__ bias) {
    extern __shared__ __align__(16) char smem_raw[];
    u64* s_p = (u64*)smem_raw;          // [ch][row][32]: A 0..15, B 16..31
    u64* s_w = s_p + 15360;             // [co][cin][ky][kx] strides 400/25/5/1

    const int img = blockIdx.x;
    const int tid = threadIdx.x;        // 384

    const float* xim = g_pool1 + (size_t)img * 14400;
    for (int i = tid; i < 15360; i += 384) {
        int c    = i / 960;
        int rem  = i % 960;
        int row  = rem >> 5;
        int slot = rem & 31;
        const float* gr = xim + c * 900 + row * 30;
        u64 v;
        if (slot < 16) {                // A: cols (2p, 2p+1)
            int p = slot;
            float lo = (2 * p < 30)     ? gr[2 * p]     : 0.0f;
            float hi = (2 * p + 1 < 30) ? gr[2 * p + 1] : 0.0f;
            v = pk2(lo, hi);
        } else {                        // B: cols (2p+1, 2p+2)
            int p = slot - 16;
            float lo = (2 * p + 1 < 30) ? gr[2 * p + 1] : 0.0f;
            float hi = (2 * p + 2 < 30) ? gr[2 * p + 2] : 0.0f;
            v = pk2(lo, hi);
        }
        s_p[i] = v;
    }
    for (int i = tid; i < 6400; i += 384) {
        float wv = w[i];
        s_w[i] = pk2(wv, wv);
    }
    __syncthreads();

    const int g = tid / 96;
    const int t = tid % 96;

    if (t < 91) {
        const int pr  = t / 7;          // pooled row 0..12
        const int pcp = t % 7;          // pooled col pair 0..6
        const int oy  = 2 * pr;
        const int co0 = 4 * g;
        const int base = oy * 32 + 2 * pcp;

        u64 acc[4][2][2];
        #pragma unroll
        for (int co = 0; co < 4; co++) {
            float bv = __ldg(bias + co0 + co);
            u64 bb = pk2(bv, bv);
            acc[co][0][0] = bb; acc[co][0][1] = bb;
            acc[co][1][0] = bb; acc[co][1][1] = bb;
        }

        const u64* rp = s_p + base;
        const u64* wB = s_w + co0 * 400;
        #pragma unroll 1
        for (int cin = 0; cin < 16; cin++) {
            u64 Xa0, Xa1, Xa2, Xa3, Xb0, Xb1, Xb2;
            u64 Ya0, Ya1, Ya2, Ya3, Yb0, Yb1, Yb2;
            LOADR(X, rp, 16)            // row oy
            LOADR(Y, rp + 32, 16)       // row oy+1
            KYS(0, 400, X, Y)
            LOADR(X, rp + 64, 16)
            KYS(1, 400, Y, X)
            LOADR(Y, rp + 96, 16)
            KYS(2, 400, X, Y)
            LOADR(X, rp + 128, 16)
            KYS(3, 400, Y, X)
            LOADR(Y, rp + 160, 16)
            KYS(4, 400, X, Y)
            rp += 960;
            wB += 25;
        }

        const float c0 = __ldg(coef + 0), c1 = __ldg(coef + 1),
                    c2 = __ldg(coef + 2), c3 = __ldg(coef + 3),
                    c4 = __ldg(coef + 4);
        const float a0 = c0 - 2.0f * c2 + 12.0f * c4;
        const float a1 = 2.0f * c1 - 12.0f * c3;
        const float a2 = 4.0f * c2 - 48.0f * c4;
        const float a3 = 8.0f * c3;
        const float a4 = 16.0f * c4;

        #pragma unroll
        for (int co = 0; co < 4; co++) {
            float2 r0j0 = upk(acc[co][0][0]), r0j1 = upk(acc[co][0][1]);
            float2 r1j0 = upk(acc[co][1][0]), r1j1 = upk(acc[co][1][1]);
            float m0 = fmaxf(fmaxf(herm4(r0j0.x, a0, a1, a2, a3, a4),
                                   herm4(r0j0.y, a0, a1, a2, a3, a4)),
                             fmaxf(herm4(r1j0.x, a0, a1, a2, a3, a4),
                                   herm4(r1j0.y, a0, a1, a2, a3, a4)));
            float m1 = fmaxf(fmaxf(herm4(r0j1.x, a0, a1, a2, a3, a4),
                                   herm4(r0j1.y, a0, a1, a2, a3, a4)),
                             fmaxf(herm4(r1j1.x, a0, a1, a2, a3, a4),
                                   herm4(r1j1.y, a0, a1, a2, a3, a4)));
            int idx = ((img * 16 + co0 + co) * 13 + pr) * 13 + 2 * pcp;
            g_pool2[idx] = m0;
            if (2 * pcp + 1 < 13) g_pool2[idx + 1] = m1;
        }
    }
}

// ---------------------------------------------------------------------------
// Kernel 3: FC [512,2704] @ [2704,10]^T + bias
// ---------------------------------------------------------------------------
__global__ void __launch_bounds__(128)
fc_kernel(const float* __restrict__ w,
          const float* __restrict__ bias,
          float* __restrict__ out) {
    const int img = blockIdx.x;
    const int tid = threadIdx.x;   // 128

    const float* xv = g_pool2 + (size_t)img * 2704;
    float p[10];
    #pragma unroll
    for (int o = 0; o < 10; o++) p[o] = 0.0f;

    for (int k = tid; k < 2704; k += 128) {
        float v = xv[k];
        #pragma unroll
        for (int o = 0; o < 10; o++) p[o] = fmaf(v, w[o * 2704 + k], p[o]);
    }

    __shared__ float red[4][10];
    const int lane = tid & 31, wrp = tid >> 5;
    #pragma unroll
    for (int o = 0; o < 10; o++) {
        float v = p[o];
        #pragma unroll
        for (int s = 16; s > 0; s >>= 1)
            v += __shfl_down_sync(0xffffffffu, v, s);
        if (lane == 0) red[wrp][o] = v;
    }
    __syncthreads();
    if (tid < 10)
        out[img * 10 + tid] =
            red[0][tid] + red[1][tid] + red[2][tid] + red[3][tid] + bias[tid];
}

// ---------------------------------------------------------------------------
extern "C" void kernel_launch(void* const* d_in, const int* in_sizes, int n_in,
                              void* d_out, int out_size) {
    const float* x       = (const float*)d_in[0];
    const float* coef    = (const float*)d_in[1];
    const float* conv1_w = (const float*)d_in[2];
    const float* conv1_b = (const float*)d_in[3];
    const float* conv2_w = (const float*)d_in[4];
    const float* conv2_b = (const float*)d_in[5];
    const float* fc1_w   = (const float*)d_in[6];
    const float* fc1_b   = (const float*)d_in[7];
    float* out = (float*)d_out;

    const int smem1 = (3072 + 1200) * 8;     // 34,176 B
    const int smem2 = (15360 + 6400) * 8;    // 174,080 B

    cudaFuncSetAttribute(conv2_fused_kernel,
                         cudaFuncAttributeMaxDynamicSharedMemorySize, smem2);

    conv1_fused_kernel<<<B_IMG * 5, 384, smem1>>>(x, coef, conv1_w, conv1_b);
    conv2_fused_kernel<<<B_IMG, 384, smem2>>>(coef, conv2_w, conv2_b);
    fc_kernel<<<B_IMG, 128>>>(fc1_w, fc1_b, out);
}

// round 15
// speedup vs baseline: 1.3652x; 1.3652x over previous
#include <cuda_runtime.h>
#include <cuda_bf16.h>
#include <math.h>
#include <stdint.h>

// ---------------------------------------------------------------------------
// ConvNet: conv(3->16,5x5) -> hermite -> pool2 -> conv(16->16,5x5) -> hermite
//          -> pool2 -> FC(2704->10).  B=512, input 3x64x64.
// Round 14: tcgen05 unavailable (harness targets base sm_100). conv2 moved to
// warp-level mma.sync m16n8k16 bf16 (HMMA fallback path), hi/lo split for
// fp32-grade accuracy. conv1 = known-good R1 scalar kernel.
// ---------------------------------------------------------------------------

#define B_IMG 512

__device__ float g_pool1[B_IMG * 16 * 30 * 30];
__device__ float g_pool2[B_IMG * 16 * 13 * 13];

__device__ __forceinline__ float herm4(float x, float a0, float a1, float a2,
                                       float a3, float a4) {
    return fmaf(fmaf(fmaf(fmaf(a4, x, a3), x, a2), x, a1), x, a0);
}

// mma.sync m16n8k16 row.col f32.bf16.bf16.f32 (sm_80+, HMMA on sm_100)
#define MMA16816(D0, D1, D2, D3, A0, A1, A2, A3, Bb0, Bb1)                   \
    asm volatile(                                                            \
        "mma.sync.aligned.m16n8k16.row.col.f32.bf16.bf16.f32 "               \
        "{%0,%1,%2,%3}, {%4,%5,%6,%7}, {%8,%9}, {%0,%1,%2,%3};"              \
        : "+f"(D0), "+f"(D1), "+f"(D2), "+f"(D3)                             \
        : "r"(A0), "r"(A1), "r"(A2), "r"(A3), "r"(Bb0), "r"(Bb1))

// ---------------------------------------------------------------------------
// Kernel 1: conv1 + bias + hermite + maxpool2 (R1 scalar, known-good)
// ---------------------------------------------------------------------------
__global__ void conv1_fused_kernel(const float* __restrict__ x,
                                   const float* __restrict__ coef,
                                   const float* __restrict__ w,
                                   const float* __restrict__ bias) {
    extern __shared__ float smem[];
    float* s_in = smem;               // 3*16*64 = 3072
    float* s_w  = smem + 3 * 16 * 64; // 1200
    float* s_b  = s_w + 1200;         // 16

    const int img  = blockIdx.x / 5;
    const int band = blockIdx.x % 5;
    const int tid  = threadIdx.x;     // 192

    const float* xim = x + (size_t)img * 3 * 64 * 64;
    const int row0 = band * 12;
    for (int i = tid; i < 3 * 16 * 64; i += 192) {
        int c   = i / (16 * 64);
        int rr  = (i / 64) % 16;
        int col = i % 64;
        s_in[i] = xim[c * 4096 + (row0 + rr) * 64 + col];
    }
    for (int i = tid; i < 1200; i += 192) s_w[i] = w[i];
    if (tid < 16) s_b[tid] = bias[tid];
    __syncthreads();

    const float c0 = __ldg(coef + 0), c1 = __ldg(coef + 1), c2 = __ldg(coef + 2),
                c3 = __ldg(coef + 3), c4 = __ldg(coef + 4);
    const float a0 = c0 - 2.0f * c2 + 12.0f * c4;
    const float a1 = 2.0f * c1 - 12.0f * c3;
    const float a2 = 4.0f * c2 - 48.0f * c4;
    const float a3 = 8.0f * c3;
    const float a4 = 16.0f * c4;

    if (tid < 180) {
        const int pyl = tid / 30;
        const int px  = tid % 30;
        const int oy  = 2 * pyl;
        const int ox  = 2 * px;

        #pragma unroll 1
        for (int chunk = 0; chunk < 2; chunk++) {
            float acc[8][4];
            #pragma unroll
            for (int co = 0; co < 8; co++) {
                float bv = s_b[chunk * 8 + co];
                acc[co][0] = bv; acc[co][1] = bv; acc[co][2] = bv; acc[co][3] = bv;
            }

            #pragma unroll 1
            for (int cin = 0; cin < 3; cin++) {
                const float* rowp = s_in + cin * 16 * 64 + oy * 64 + ox;
                float va[6], vb[6];
                #pragma unroll
                for (int k = 0; k < 6; k++) va[k] = rowp[k];
                rowp += 64;
                #pragma unroll
                for (int k = 0; k < 6; k++) vb[k] = rowp[k];

                const float* wp = s_w + (chunk * 8) * 75 + cin * 25;
                #pragma unroll
                for (int ky = 0; ky < 5; ky++) {
                    if (ky) {
                        #pragma unroll
                        for (int k = 0; k < 6; k++) va[k] = vb[k];
                        rowp += 64;
                        #pragma unroll
                        for (int k = 0; k < 6; k++) vb[k] = rowp[k];
                    }
                    #pragma unroll
                    for (int co = 0; co < 8; co++) {
                        #pragma unroll
                        for (int kx = 0; kx < 5; kx++) {
                            float wv = wp[co * 75 + ky * 5 + kx];
                            acc[co][0] = fmaf(va[kx],     wv, acc[co][0]);
                            acc[co][1] = fmaf(va[kx + 1], wv, acc[co][1]);
                            acc[co][2] = fmaf(vb[kx],     wv, acc[co][2]);
                            acc[co][3] = fmaf(vb[kx + 1], wv, acc[co][3]);
                        }
                    }
                }
            }

            const int py = band * 6 + pyl;
            #pragma unroll
            for (int co = 0; co < 8; co++) {
                float h0 = herm4(acc[co][0], a0, a1, a2, a3, a4);
                float h1 = herm4(acc[co][1], a0, a1, a2, a3, a4);
                float h2 = herm4(acc[co][2], a0, a1, a2, a3, a4);
                float h3 = herm4(acc[co][3], a0, a1, a2, a3, a4);
                float m = fmaxf(fmaxf(h0, h1), fmaxf(h2, h3));
                g_pool1[((img * 16 + chunk * 8 + co) * 30 + py) * 30 + px] = m;
            }
        }
    }
}

// ---------------------------------------------------------------------------
// Kernel 2: conv2 via mma.sync m16n8k16 bf16 (hi/lo split) + bias + hermite
//           + maxpool2. Grid: 512 CTAs (one image), 256 threads (8 warps).
// GEMM: D[676 pos, 16 co], K = 400 = 25 taps x 16 cin (one K-slab per tap).
// A frags gathered from smem [y*30+x][cin] bf16; B in smem [ks][co][cin].
// Smem (bytes):
//   in_hi 0..28800 | in_lo 28800..57600 | Bhi 57600..70400 | Blo 70400..83200
//   buf (herm results, [co][676] f32) 83200..126464 | bias 126464..126528
// ---------------------------------------------------------------------------
#define C2_SMEM 126528

__global__ void __launch_bounds__(256)
conv2_mma_kernel(const float* __restrict__ coef,
                 const float* __restrict__ w,
                 const float* __restrict__ bias) {
    extern __shared__ __align__(16) char sm[];
    __nv_bfloat16* shi  = (__nv_bfloat16*)(sm);
    __nv_bfloat16* slo  = (__nv_bfloat16*)(sm + 28800);
    __nv_bfloat16* bwh  = (__nv_bfloat16*)(sm + 57600);
    __nv_bfloat16* bwl  = (__nv_bfloat16*)(sm + 70400);
    float*         buf  = (float*)(sm + 83200);      // [co][676]
    float*         sbia = (float*)(sm + 126464);

    const int tid = threadIdx.x;
    const int img = blockIdx.x;

    // ---- input -> bf16 hi/lo, layout [pos=y*30+x][cin] ----
    const float* xim = g_pool1 + (size_t)img * 14400;
    for (int i = tid; i < 14400; i += 256) {
        int cin = i / 900, rem = i % 900;
        float v = xim[i];
        __nv_bfloat16 h = __float2bfloat16(v);
        __nv_bfloat16 l = __float2bfloat16(v - __bfloat162float(h));
        int d = rem * 16 + cin;
        shi[d] = h;
        slo[d] = l;
    }
    // ---- weights -> bf16 hi/lo, layout [ks][co][cin] ----
    for (int i = tid; i < 6400; i += 256) {
        int ks = i / 256, r = i % 256, co = r / 16, cin = r % 16;
        float v = w[co * 400 + cin * 25 + ks];
        __nv_bfloat16 h = __float2bfloat16(v);
        __nv_bfloat16 l = __float2bfloat16(v - __bfloat162float(h));
        bwh[i] = h;
        bwl[i] = l;
    }
    if (tid < 16) sbia[tid] = bias[tid];
    __syncthreads();

    const float c0 = __ldg(coef + 0), c1 = __ldg(coef + 1), c2 = __ldg(coef + 2),
                c3 = __ldg(coef + 3), c4 = __ldg(coef + 4);
    const float a0 = c0 - 2.0f * c2 + 12.0f * c4;
    const float a1 = 2.0f * c1 - 12.0f * c3;
    const float a2 = 4.0f * c2 - 48.0f * c4;
    const float a3 = 8.0f * c3;
    const float a4 = 16.0f * c4;

    const int warp = tid >> 5, lane = tid & 31;
    const int g = lane >> 2, t4 = lane & 3;
    const uint32_t* ih = (const uint32_t*)shi;   // 8 u32 per position row
    const uint32_t* il = (const uint32_t*)slo;
    const uint32_t* wh = (const uint32_t*)bwh;   // [ks][co][8 u32? no: co*8]
    const uint32_t* wl = (const uint32_t*)bwl;

    // 43 M-tiles of 16 positions (676 valid)
    #pragma unroll 1
    for (int tile = warp; tile < 43; tile += 8) {
        const int p0 = tile * 16 + g;
        const int p1 = p0 + 8;
        const bool v0 = p0 < 676, v1 = p1 < 676;
        const int q0 = v0 ? p0 : 675, q1 = v1 ? p1 : 675;
        const int e0 = (q0 / 26) * 30 + (q0 % 26);
        const int e1 = (q1 / 26) * 30 + (q1 % 26);

        float d00 = 0.f, d01 = 0.f, d02 = 0.f, d03 = 0.f;   // cols 0..7
        float d10 = 0.f, d11 = 0.f, d12 = 0.f, d13 = 0.f;   // cols 8..15

        #pragma unroll
        for (int ks = 0; ks < 25; ks++) {
            const int off = (ks / 5) * 30 + (ks % 5);       // compile-time
            const int r0 = (e0 + off) * 8 + t4;
            const int r1 = (e1 + off) * 8 + t4;
            uint32_t ah0 = ih[r0],     ah1 = ih[r1];
            uint32_t ah2 = ih[r0 + 4], ah3 = ih[r1 + 4];
            uint32_t al0 = il[r0],     al1 = il[r1];
            uint32_t al2 = il[r0 + 4], al3 = il[r1 + 4];

            const int wb = ks * 128 + g * 8 + t4;           // half0: co 0..7
            uint32_t bh0 = wh[wb],      bh1 = wh[wb + 4];
            uint32_t bl0 = wl[wb],      bl1 = wl[wb + 4];
            MMA16816(d00, d01, d02, d03, ah0, ah1, ah2, ah3, bh0, bh1);
            MMA16816(d00, d01, d02, d03, ah0, ah1, ah2, ah3, bl0, bl1);
            MMA16816(d00, d01, d02, d03, al0, al1, al2, al3, bh0, bh1);

            const int wb2 = wb + 64;                        // half1: co 8..15
            uint32_t ch0 = wh[wb2],     ch1 = wh[wb2 + 4];
            uint32_t cl0 = wl[wb2],     cl1 = wl[wb2 + 4];
            MMA16816(d10, d11, d12, d13, ah0, ah1, ah2, ah3, ch0, ch1);
            MMA16816(d10, d11, d12, d13, ah0, ah1, ah2, ah3, cl0, cl1);
            MMA16816(d10, d11, d12, d13, al0, al1, al2, al3, ch0, ch1);
        }

        // write herm(bias+conv) into buf[co][pos]
        const int coA = t4 * 2;          // cols t4*2, t4*2+1 (half0)
        if (v0) {
            buf[coA * 676 + p0]       = herm4(d00 + sbia[coA],     a0, a1, a2, a3, a4);
            buf[(coA + 1) * 676 + p0] = herm4(d01 + sbia[coA + 1], a0, a1, a2, a3, a4);
            buf[(coA + 8) * 676 + p0] = herm4(d10 + sbia[coA + 8], a0, a1, a2, a3, a4);
            buf[(coA + 9) * 676 + p0] = herm4(d11 + sbia[coA + 9], a0, a1, a2, a3, a4);
        }
        if (v1) {
            buf[coA * 676 + p1]       = herm4(d02 + sbia[coA],     a0, a1, a2, a3, a4);
            buf[(coA + 1) * 676 + p1] = herm4(d03 + sbia[coA + 1], a0, a1, a2, a3, a4);
            buf[(coA + 8) * 676 + p1] = herm4(d12 + sbia[coA + 8], a0, a1, a2, a3, a4);
            buf[(coA + 9) * 676 + p1] = herm4(d13 + sbia[coA + 9], a0, a1, a2, a3, a4);
        }
    }
    __syncthreads();

    // ---- 2x2 max-pool over buf -> g_pool2 ----
    for (int i = tid; i < 2704; i += 256) {
        int co = i / 169, pp = i % 169;
        int py = pp / 13, px = pp % 13;
        const float* bp = buf + co * 676 + (2 * py) * 26 + 2 * px;
        float m = fmaxf(fmaxf(bp[0], bp[1]), fmaxf(bp[26], bp[27]));
        g_pool2[((img * 16 + co) * 13 + py) * 13 + px] = m;
    }
}

// ---------------------------------------------------------------------------
// Kernel 3: FC [512,2704] @ [2704,10]^T + bias
// ---------------------------------------------------------------------------
__global__ void __launch_bounds__(128)
fc_kernel(const float* __restrict__ w,
          const float* __restrict__ bias,
          float* __restrict__ out) {
    const int img = blockIdx.x;
    const int tid = threadIdx.x;

    const float* xv = g_pool2 + (size_t)img * 2704;
    float p[10];
    #pragma unroll
    for (int o = 0; o < 10; o++) p[o] = 0.0f;

    for (int k = tid; k < 2704; k += 128) {
        float v = xv[k];
        #pragma unroll
        for (int o = 0; o < 10; o++) p[o] = fmaf(v, w[o * 2704 + k], p[o]);
    }

    __shared__ float red[4][10];
    const int lane = tid & 31, wrp = tid >> 5;
    #pragma unroll
    for (int o = 0; o < 10; o++) {
        float v = p[o];
        #pragma unroll
        for (int s = 16; s > 0; s >>= 1)
            v += __shfl_down_sync(0xffffffffu, v, s);
        if (lane == 0) red[wrp][o] = v;
    }
    __syncthreads();
    if (tid < 10)
        out[img * 10 + tid] =
            red[0][tid] + red[1][tid] + red[2][tid] + red[3][tid] + bias[tid];
}

// ---------------------------------------------------------------------------
extern "C" void kernel_launch(void* const* d_in, const int* in_sizes, int n_in,
                              void* d_out, int out_size) {
    const float* x       = (const float*)d_in[0];
    const float* coef    = (const float*)d_in[1];
    const float* conv1_w = (const float*)d_in[2];
    const float* conv1_b = (const float*)d_in[3];
    const float* conv2_w = (const float*)d_in[4];
    const float* conv2_b = (const float*)d_in[5];
    const float* fc1_w   = (const float*)d_in[6];
    const float* fc1_b   = (const float*)d_in[7];
    float* out = (float*)d_out;

    const int smem1 = (3 * 16 * 64 + 1200 + 16) * sizeof(float);   // ~17.2 KB

    cudaFuncSetAttribute(conv2_mma_kernel,
                         cudaFuncAttributeMaxDynamicSharedMemorySize, C2_SMEM);

    conv1_fused_kernel<<<B_IMG * 5, 192, smem1>>>(x, coef, conv1_w, conv1_b);
    conv2_mma_kernel<<<B_IMG, 256, C2_SMEM>>>(coef, conv2_w, conv2_b);
    fc_kernel<<<B_IMG, 128>>>(fc1_w, fc1_b, out);
}

// round 16
// speedup vs baseline: 1.5521x; 1.1369x over previous
#include <cuda_runtime.h>
#include <cuda_bf16.h>
#include <math.h>
#include <stdint.h>

// ---------------------------------------------------------------------------
// ConvNet: conv(3->16,5x5) -> hermite -> pool2 -> conv(16->16,5x5) -> hermite
//          -> pool2 -> FC(2704->10).  B=512, input 3x64x64.
// Round 15: conv2 mma kernel register-blocked: each warp owns 6 M-tiles with
// persistent accumulators; ks outer loop loads B fragments ONCE per ks and
// reuses them across the 6 tiles (was: B reloaded per tile -> 16 LDS/tile).
// conv1 = known-good R1 scalar kernel. Fragment mapping identical to R14.
// ---------------------------------------------------------------------------

#define B_IMG 512

__device__ float g_pool1[B_IMG * 16 * 30 * 30];
__device__ float g_pool2[B_IMG * 16 * 13 * 13];

__device__ __forceinline__ float herm4(float x, float a0, float a1, float a2,
                                       float a3, float a4) {
    return fmaf(fmaf(fmaf(fmaf(a4, x, a3), x, a2), x, a1), x, a0);
}

// mma.sync m16n8k16 row.col f32.bf16.bf16.f32 (sm_80+, HMMA on sm_100)
#define MMA16816(D0, D1, D2, D3, A0, A1, A2, A3, Bb0, Bb1)                   \
    asm volatile(                                                            \
        "mma.sync.aligned.m16n8k16.row.col.f32.bf16.bf16.f32 "               \
        "{%0,%1,%2,%3}, {%4,%5,%6,%7}, {%8,%9}, {%0,%1,%2,%3};"              \
        : "+f"(D0), "+f"(D1), "+f"(D2), "+f"(D3)                             \
        : "r"(A0), "r"(A1), "r"(A2), "r"(A3), "r"(Bb0), "r"(Bb1))

// ---------------------------------------------------------------------------
// Kernel 1: conv1 + bias + hermite + maxpool2 (R1 scalar, known-good)
// ---------------------------------------------------------------------------
__global__ void conv1_fused_kernel(const float* __restrict__ x,
                                   const float* __restrict__ coef,
                                   const float* __restrict__ w,
                                   const float* __restrict__ bias) {
    extern __shared__ float smem[];
    float* s_in = smem;               // 3*16*64 = 3072
    float* s_w  = smem + 3 * 16 * 64; // 1200
    float* s_b  = s_w + 1200;         // 16

    const int img  = blockIdx.x / 5;
    const int band = blockIdx.x % 5;
    const int tid  = threadIdx.x;     // 192

    const float* xim = x + (size_t)img * 3 * 64 * 64;
    const int row0 = band * 12;
    for (int i = tid; i < 3 * 16 * 64; i += 192) {
        int c   = i / (16 * 64);
        int rr  = (i / 64) % 16;
        int col = i % 64;
        s_in[i] = xim[c * 4096 + (row0 + rr) * 64 + col];
    }
    for (int i = tid; i < 1200; i += 192) s_w[i] = w[i];
    if (tid < 16) s_b[tid] = bias[tid];
    __syncthreads();

    const float c0 = __ldg(coef + 0), c1 = __ldg(coef + 1), c2 = __ldg(coef + 2),
                c3 = __ldg(coef + 3), c4 = __ldg(coef + 4);
    const float a0 = c0 - 2.0f * c2 + 12.0f * c4;
    const float a1 = 2.0f * c1 - 12.0f * c3;
    const float a2 = 4.0f * c2 - 48.0f * c4;
    const float a3 = 8.0f * c3;
    const float a4 = 16.0f * c4;

    if (tid < 180) {
        const int pyl = tid / 30;
        const int px  = tid % 30;
        const int oy  = 2 * pyl;
        const int ox  = 2 * px;

        #pragma unroll 1
        for (int chunk = 0; chunk < 2; chunk++) {
            float acc[8][4];
            #pragma unroll
            for (int co = 0; co < 8; co++) {
                float bv = s_b[chunk * 8 + co];
                acc[co][0] = bv; acc[co][1] = bv; acc[co][2] = bv; acc[co][3] = bv;
            }

            #pragma unroll 1
            for (int cin = 0; cin < 3; cin++) {
                const float* rowp = s_in + cin * 16 * 64 + oy * 64 + ox;
                float va[6], vb[6];
                #pragma unroll
                for (int k = 0; k < 6; k++) va[k] = rowp[k];
                rowp += 64;
                #pragma unroll
                for (int k = 0; k < 6; k++) vb[k] = rowp[k];

                const float* wp = s_w + (chunk * 8) * 75 + cin * 25;
                #pragma unroll
                for (int ky = 0; ky < 5; ky++) {
                    if (ky) {
                        #pragma unroll
                        for (int k = 0; k < 6; k++) va[k] = vb[k];
                        rowp += 64;
                        #pragma unroll
                        for (int k = 0; k < 6; k++) vb[k] = rowp[k];
                    }
                    #pragma unroll
                    for (int co = 0; co < 8; co++) {
                        #pragma unroll
                        for (int kx = 0; kx < 5; kx++) {
                            float wv = wp[co * 75 + ky * 5 + kx];
                            acc[co][0] = fmaf(va[kx],     wv, acc[co][0]);
                            acc[co][1] = fmaf(va[kx + 1], wv, acc[co][1]);
                            acc[co][2] = fmaf(vb[kx],     wv, acc[co][2]);
                            acc[co][3] = fmaf(vb[kx + 1], wv, acc[co][3]);
                        }
                    }
                }
            }

            const int py = band * 6 + pyl;
            #pragma unroll
            for (int co = 0; co < 8; co++) {
                float h0 = herm4(acc[co][0], a0, a1, a2, a3, a4);
                float h1 = herm4(acc[co][1], a0, a1, a2, a3, a4);
                float h2 = herm4(acc[co][2], a0, a1, a2, a3, a4);
                float h3 = herm4(acc[co][3], a0, a1, a2, a3, a4);
                float m = fmaxf(fmaxf(h0, h1), fmaxf(h2, h3));
                g_pool1[((img * 16 + chunk * 8 + co) * 30 + py) * 30 + px] = m;
            }
        }
    }
}

// ---------------------------------------------------------------------------
// Kernel 2: conv2 via mma.sync m16n8k16 bf16 (hi/lo split), register-blocked.
// Grid: 512 CTAs (one image), 256 threads (8 warps).
// Each warp owns 6 M-tiles (tiles warp+8j, j=0..5; 48 tiles cover 43 real).
// ks outer: B frags loaded once per ks, reused across the 6 tiles.
// Smem (bytes):
//   in_hi 0..28800 | in_lo 28800..57600 | Bhi 57600..70400 | Blo 70400..83200
//   buf ([co][676] f32) 83200..126464 | bias 126464..126528
// ---------------------------------------------------------------------------
#define C2_SMEM 126528

__global__ void __launch_bounds__(256)
conv2_mma_kernel(const float* __restrict__ coef,
                 const float* __restrict__ w,
                 const float* __restrict__ bias) {
    extern __shared__ __align__(16) char sm[];
    __nv_bfloat16* shi  = (__nv_bfloat16*)(sm);
    __nv_bfloat16* slo  = (__nv_bfloat16*)(sm + 28800);
    __nv_bfloat16* bwh  = (__nv_bfloat16*)(sm + 57600);
    __nv_bfloat16* bwl  = (__nv_bfloat16*)(sm + 70400);
    float*         buf  = (float*)(sm + 83200);      // [co][676]
    float*         sbia = (float*)(sm + 126464);

    const int tid = threadIdx.x;
    const int img = blockIdx.x;

    // ---- input -> bf16 hi/lo, layout [pos=y*30+x][cin] ----
    const float* xim = g_pool1 + (size_t)img * 14400;
    for (int i = tid; i < 14400; i += 256) {
        int cin = i / 900, rem = i % 900;
        float v = xim[i];
        __nv_bfloat16 h = __float2bfloat16(v);
        __nv_bfloat16 l = __float2bfloat16(v - __bfloat162float(h));
        int d = rem * 16 + cin;
        shi[d] = h;
        slo[d] = l;
    }
    // ---- weights -> bf16 hi/lo, layout [ks][co][cin] ----
    for (int i = tid; i < 6400; i += 256) {
        int ks = i / 256, r = i % 256, co = r / 16, cin = r % 16;
        float v = w[co * 400 + cin * 25 + ks];
        __nv_bfloat16 h = __float2bfloat16(v);
        __nv_bfloat16 l = __float2bfloat16(v - __bfloat162float(h));
        bwh[i] = h;
        bwl[i] = l;
    }
    if (tid < 16) sbia[tid] = bias[tid];
    __syncthreads();

    const float c0 = __ldg(coef + 0), c1 = __ldg(coef + 1), c2 = __ldg(coef + 2),
                c3 = __ldg(coef + 3), c4 = __ldg(coef + 4);
    const float a0 = c0 - 2.0f * c2 + 12.0f * c4;
    const float a1 = 2.0f * c1 - 12.0f * c3;
    const float a2 = 4.0f * c2 - 48.0f * c4;
    const float a3 = 8.0f * c3;
    const float a4 = 16.0f * c4;

    const int warp = tid >> 5, lane = tid & 31;
    const int g = lane >> 2, t4 = lane & 3;
    const uint32_t* ih = (const uint32_t*)shi;   // 8 u32 per position
    const uint32_t* il = (const uint32_t*)slo;
    const uint32_t* wh = (const uint32_t*)bwh;
    const uint32_t* wl = (const uint32_t*)bwl;

    // per-warp tile set: tiles warp + 8j (j = 0..5)
    int e0[6], e1[6];
    bool v0[6], v1[6];
    int p0a[6], p1a[6];
    #pragma unroll
    for (int j = 0; j < 6; j++) {
        int tile = warp + 8 * j;            // 0..47
        int p0 = tile * 16 + g;
        int p1 = p0 + 8;
        v0[j] = p0 < 676; v1[j] = p1 < 676;
        p0a[j] = p0; p1a[j] = p1;
        int q0 = v0[j] ? p0 : 675, q1 = v1[j] ? p1 : 675;
        e0[j] = (q0 / 26) * 30 + (q0 % 26);
        e1[j] = (q1 / 26) * 30 + (q1 % 26);
    }

    float acc[6][8];
    #pragma unroll
    for (int j = 0; j < 6; j++)
        #pragma unroll
        for (int k = 0; k < 8; k++) acc[j][k] = 0.0f;

    #pragma unroll 1
    for (int ks = 0; ks < 25; ks++) {
        const int off = (ks / 5) * 30 + (ks % 5);
        const int wb = ks * 128 + g * 8 + t4;
        const uint32_t bh0 = wh[wb],      bh1 = wh[wb + 4];
        const uint32_t bl0 = wl[wb],      bl1 = wl[wb + 4];
        const uint32_t ch0 = wh[wb + 64], ch1 = wh[wb + 68];
        const uint32_t cl0 = wl[wb + 64], cl1 = wl[wb + 68];

        #pragma unroll
        for (int j = 0; j < 6; j++) {
            const int r0 = (e0[j] + off) * 8 + t4;
            const int r1 = (e1[j] + off) * 8 + t4;
            uint32_t ah0 = ih[r0],     ah1 = ih[r1];
            uint32_t ah2 = ih[r0 + 4], ah3 = ih[r1 + 4];
            uint32_t al0 = il[r0],     al1 = il[r1];
            uint32_t al2 = il[r0 + 4], al3 = il[r1 + 4];

            MMA16816(acc[j][0], acc[j][1], acc[j][2], acc[j][3],
                     ah0, ah1, ah2, ah3, bh0, bh1);
            MMA16816(acc[j][0], acc[j][1], acc[j][2], acc[j][3],
                     ah0, ah1, ah2, ah3, bl0, bl1);
            MMA16816(acc[j][0], acc[j][1], acc[j][2], acc[j][3],
                     al0, al1, al2, al3, bh0, bh1);

            MMA16816(acc[j][4], acc[j][5], acc[j][6], acc[j][7],
                     ah0, ah1, ah2, ah3, ch0, ch1);
            MMA16816(acc[j][4], acc[j][5], acc[j][6], acc[j][7],
                     ah0, ah1, ah2, ah3, cl0, cl1);
            MMA16816(acc[j][4], acc[j][5], acc[j][6], acc[j][7],
                     al0, al1, al2, al3, ch0, ch1);
        }
    }

    // ---- epilogue: bias + hermite into buf ----
    const int coA = t4 * 2;
    #pragma unroll
    for (int j = 0; j < 6; j++) {
        if (v0[j]) {
            buf[coA * 676 + p0a[j]]       = herm4(acc[j][0] + sbia[coA],     a0, a1, a2, a3, a4);
            buf[(coA + 1) * 676 + p0a[j]] = herm4(acc[j][1] + sbia[coA + 1], a0, a1, a2, a3, a4);
            buf[(coA + 8) * 676 + p0a[j]] = herm4(acc[j][4] + sbia[coA + 8], a0, a1, a2, a3, a4);
            buf[(coA + 9) * 676 + p0a[j]] = herm4(acc[j][5] + sbia[coA + 9], a0, a1, a2, a3, a4);
        }
        if (v1[j]) {
            buf[coA * 676 + p1a[j]]       = herm4(acc[j][2] + sbia[coA],     a0, a1, a2, a3, a4);
            buf[(coA + 1) * 676 + p1a[j]] = herm4(acc[j][3] + sbia[coA + 1], a0, a1, a2, a3, a4);
            buf[(coA + 8) * 676 + p1a[j]] = herm4(acc[j][6] + sbia[coA + 8], a0, a1, a2, a3, a4);
            buf[(coA + 9) * 676 + p1a[j]] = herm4(acc[j][7] + sbia[coA + 9], a0, a1, a2, a3, a4);
        }
    }
    __syncthreads();

    // ---- 2x2 max-pool over buf -> g_pool2 ----
    for (int i = tid; i < 2704; i += 256) {
        int co = i / 169, pp = i % 169;
        int py = pp / 13, px = pp % 13;
        const float* bp = buf + co * 676 + (2 * py) * 26 + 2 * px;
        float m = fmaxf(fmaxf(bp[0], bp[1]), fmaxf(bp[26], bp[27]));
        g_pool2[((img * 16 + co) * 13 + py) * 13 + px] = m;
    }
}

// ---------------------------------------------------------------------------
// Kernel 3: FC [512,2704] @ [2704,10]^T + bias
// ---------------------------------------------------------------------------
__global__ void __launch_bounds__(128)
fc_kernel(const float* __restrict__ w,
          const float* __restrict__ bias,
          float* __restrict__ out) {
    const int img = blockIdx.x;
    const int tid = threadIdx.x;

    const float* xv = g_pool2 + (size_t)img * 2704;
    float p[10];
    #pragma unroll
    for (int o = 0; o < 10; o++) p[o] = 0.0f;

    for (int k = tid; k < 2704; k += 128) {
        float v = xv[k];
        #pragma unroll
        for (int o = 0; o < 10; o++) p[o] = fmaf(v, w[o * 2704 + k], p[o]);
    }

    __shared__ float red[4][10];
    const int lane = tid & 31, wrp = tid >> 5;
    #pragma unroll
    for (int o = 0; o < 10; o++) {
        float v = p[o];
        #pragma unroll
        for (int s = 16; s > 0; s >>= 1)
            v += __shfl_down_sync(0xffffffffu, v, s);
        if (lane == 0) red[wrp][o] = v;
    }
    __syncthreads();
    if (tid < 10)
        out[img * 10 + tid] =
            red[0][tid] + red[1][tid] + red[2][tid] + red[3][tid] + bias[tid];
}

// ---------------------------------------------------------------------------
extern "C" void kernel_launch(void* const* d_in, const int* in_sizes, int n_in,
                              void* d_out, int out_size) {
    const float* x       = (const float*)d_in[0];
    const float* coef    = (const float*)d_in[1];
    const float* conv1_w = (const float*)d_in[2];
    const float* conv1_b = (const float*)d_in[3];
    const float* conv2_w = (const float*)d_in[4];
    const float* conv2_b = (const float*)d_in[5];
    const float* fc1_w   = (const float*)d_in[6];
    const float* fc1_b   = (const float*)d_in[7];
    float* out = (float*)d_out;

    const int smem1 = (3 * 16 * 64 + 1200 + 16) * sizeof(float);   // ~17.2 KB

    cudaFuncSetAttribute(conv2_mma_kernel,
                         cudaFuncAttributeMaxDynamicSharedMemorySize, C2_SMEM);

    conv1_fused_kernel<<<B_IMG * 5, 192, smem1>>>(x, coef, conv1_w, conv1_b);
    conv2_mma_kernel<<<B_IMG, 256, C2_SMEM>>>(coef, conv2_w, conv2_b);
    fc_kernel<<<B_IMG, 128>>>(fc1_w, fc1_b, out);
}

// round 17
// speedup vs baseline: 1.7143x; 1.1045x over previous
#include <cuda_runtime.h>
#include <cuda_bf16.h>
#include <math.h>
#include <stdint.h>

// ---------------------------------------------------------------------------
// ConvNet: conv(3->16,5x5) -> hermite -> pool2 -> conv(16->16,5x5) -> hermite
//          -> pool2 -> FC(2704->10).  B=512, input 3x64x64.
// Round 16: conv1 ALSO moved to mma.sync m16n8k16 bf16 (hi/lo split).
//   K = 80 = 5 slabs (one per ky): k = kx*3+cin (15 real + 1 zero-weight pad).
//   Input stored bf16 [y][x*3+cin] + a one-element phase-shifted copy so every
//   A fragment load is an aligned LDS.32 (odd-x threads use the shifted copy).
//   Register-blocked 6 tiles/warp like the R15 conv2 kernel (77us, proven).
// conv2 / fc unchanged from R15.
// ---------------------------------------------------------------------------

#define B_IMG 512

__device__ float g_pool1[B_IMG * 16 * 30 * 30];
__device__ float g_pool2[B_IMG * 16 * 13 * 13];

__device__ __forceinline__ float herm4(float x, float a0, float a1, float a2,
                                       float a3, float a4) {
    return fmaf(fmaf(fmaf(fmaf(a4, x, a3), x, a2), x, a1), x, a0);
}

// mma.sync m16n8k16 row.col f32.bf16.bf16.f32 (sm_80+, HMMA on sm_100)
#define MMA16816(D0, D1, D2, D3, A0, A1, A2, A3, Bb0, Bb1)                   \
    asm volatile(                                                            \
        "mma.sync.aligned.m16n8k16.row.col.f32.bf16.bf16.f32 "               \
        "{%0,%1,%2,%3}, {%4,%5,%6,%7}, {%8,%9}, {%0,%1,%2,%3};"              \
        : "+f"(D0), "+f"(D1), "+f"(D2), "+f"(D3)                             \
        : "r"(A0), "r"(A1), "r"(A2), "r"(A3), "r"(Bb0), "r"(Bb1))

// ---------------------------------------------------------------------------
// Kernel 1: conv1 via mma.sync (hi/lo split) + bias + hermite + maxpool2.
// Grid: 512 imgs x 5 bands, 256 threads (8 warps).
// Band = 12 conv rows x 60 conv cols = 720 positions = 48 M-tiles (some
// columns masked). Each warp owns 6 tiles (tile = warp + 8j).
// Smem (bytes):
//   p0h 0..6464 | p1h 6464..12928 | p0l 12928..19392 | p1l 19392..25856
//   bwh 25856..28416 | bwl 28416..30976 | bias 30976..31040
//   buf ([co][12][60] f32) 31040..77120
// Input row layout: 16 rows x (64*3 bf16 = 384B) padded to ROWB=400B.
// p1* copies hold element j at index j-1 (one-element phase shift).
// ---------------------------------------------------------------------------
#define C1_SMEM 77120

__global__ void __launch_bounds__(256)
conv1_mma_kernel(const float* __restrict__ x,
                 const float* __restrict__ coef,
                 const float* __restrict__ w,
                 const float* __restrict__ bias) {
    extern __shared__ __align__(16) char sm[];
    __nv_bfloat16* p0h = (__nv_bfloat16*)(sm);
    __nv_bfloat16* p1h = (__nv_bfloat16*)(sm + 6464);
    __nv_bfloat16* p0l = (__nv_bfloat16*)(sm + 12928);
    __nv_bfloat16* p1l = (__nv_bfloat16*)(sm + 19392);
    __nv_bfloat16* bwh = (__nv_bfloat16*)(sm + 25856);
    __nv_bfloat16* bwl = (__nv_bfloat16*)(sm + 28416);
    float*         sbia = (float*)(sm + 30976);
    float*         buf  = (float*)(sm + 31040);     // [co][y:12][x:60]

    const int tid  = threadIdx.x;
    const int img  = blockIdx.x / 5;
    const int band = blockIdx.x % 5;
    const int row0 = band * 12;

    // ---- input band -> bf16 hi/lo, [r][x*3+cin], + phase-shifted copies ----
    const float* xim = x + (size_t)img * 3 * 4096;
    for (int i = tid; i < 3072; i += 256) {
        int r = i / 192, j = i % 192;               // j = x*3+cin
        int xx = j / 3, cin = j % 3;
        float v = xim[cin * 4096 + (row0 + r) * 64 + xx];
        __nv_bfloat16 h = __float2bfloat16(v);
        __nv_bfloat16 l = __float2bfloat16(v - __bfloat162float(h));
        int d = r * 200 + j;                        // 200 bf16 per row (400B)
        p0h[d] = h; p0l[d] = l;
        if (j) { p1h[d - 1] = h; p1l[d - 1] = l; }
    }
    // ---- weights -> bf16 hi/lo, [ky][co][k], k = kx*3+cin, k=15 zero ----
    for (int i = tid; i < 1280; i += 256) {         // i = ky*256 + co*16 + k
        int k = i & 15, co = (i >> 4) & 15, ky = i >> 8;
        float v = (k < 15) ? w[co * 75 + (k % 3) * 25 + ky * 5 + (k / 3)] : 0.0f;
        __nv_bfloat16 h = __float2bfloat16(v);
        __nv_bfloat16 l = __float2bfloat16(v - __bfloat162float(h));
        bwh[i] = h; bwl[i] = l;
    }
    if (tid < 16) sbia[tid] = bias[tid];
    __syncthreads();

    const float c0 = __ldg(coef + 0), c1 = __ldg(coef + 1), c2 = __ldg(coef + 2),
                c3 = __ldg(coef + 3), c4 = __ldg(coef + 4);
    const float a0 = c0 - 2.0f * c2 + 12.0f * c4;
    const float a1 = 2.0f * c1 - 12.0f * c3;
    const float a2 = 4.0f * c2 - 48.0f * c4;
    const float a3 = 8.0f * c3;
    const float a4 = 16.0f * c4;

    const int warp = tid >> 5, lane = tid & 31;
    const int g = lane >> 2, t4 = lane & 3;
    const char* baseH = (g & 1) ? (const char*)p1h : (const char*)p0h;
    const char* baseL = (g & 1) ? (const char*)p1l : (const char*)p0l;
    const int sub = (g & 1) * 2;
    const uint32_t* wh = (const uint32_t*)bwh;
    const uint32_t* wl = (const uint32_t*)bwl;

    int yA[6], x0A[6];
    #pragma unroll
    for (int j = 0; j < 6; j++) {
        int tile = warp + 8 * j;                    // 0..47
        yA[j]  = tile >> 2;                         // conv row 0..11
        x0A[j] = (tile & 3) * 16;                   // 0,16,32,48
    }

    float acc[6][8];
    #pragma unroll
    for (int j = 0; j < 6; j++)
        #pragma unroll
        for (int k = 0; k < 8; k++) acc[j][k] = 0.0f;

    #pragma unroll 1
    for (int ky = 0; ky < 5; ky++) {
        const int wb = ky * 128 + g * 8 + t4;
        const uint32_t bh0 = wh[wb],      bh1 = wh[wb + 4];
        const uint32_t bl0 = wl[wb],      bl1 = wl[wb + 4];
        const uint32_t ch0 = wh[wb + 64], ch1 = wh[wb + 68];
        const uint32_t cl0 = wl[wb + 64], cl1 = wl[wb + 68];

        #pragma unroll
        for (int j = 0; j < 6; j++) {
            const int off = (yA[j] + ky) * 400 + (x0A[j] + g) * 6 - sub + 4 * t4;
            uint32_t ah0 = *(const uint32_t*)(baseH + off);
            uint32_t ah1 = *(const uint32_t*)(baseH + off + 48);
            uint32_t ah2 = *(const uint32_t*)(baseH + off + 16);
            uint32_t ah3 = *(const uint32_t*)(baseH + off + 64);
            uint32_t al0 = *(const uint32_t*)(baseL + off);
            uint32_t al1 = *(const uint32_t*)(baseL + off + 48);
            uint32_t al2 = *(const uint32_t*)(baseL + off + 16);
            uint32_t al3 = *(const uint32_t*)(baseL + off + 64);

            MMA16816(acc[j][0], acc[j][1], acc[j][2], acc[j][3],
                     ah0, ah1, ah2, ah3, bh0, bh1);
            MMA16816(acc[j][0], acc[j][1], acc[j][2], acc[j][3],
                     ah0, ah1, ah2, ah3, bl0, bl1);
            MMA16816(acc[j][0], acc[j][1], acc[j][2], acc[j][3],
                     al0, al1, al2, al3, bh0, bh1);

            MMA16816(acc[j][4], acc[j][5], acc[j][6], acc[j][7],
                     ah0, ah1, ah2, ah3, ch0, ch1);
            MMA16816(acc[j][4], acc[j][5], acc[j][6], acc[j][7],
                     ah0, ah1, ah2, ah3, cl0, cl1);
            MMA16816(acc[j][4], acc[j][5], acc[j][6], acc[j][7],
                     al0, al1, al2, al3, ch0, ch1);
        }
    }

    // ---- epilogue: bias + hermite into buf [co][y][x] ----
    const int coA = t4 * 2;
    #pragma unroll
    for (int j = 0; j < 6; j++) {
        const int yb = yA[j] * 60;
        const int xg = x0A[j] + g;
        const int x8 = xg + 8;
        buf[coA * 720 + yb + xg]       = herm4(acc[j][0] + sbia[coA],     a0, a1, a2, a3, a4);
        buf[(coA + 1) * 720 + yb + xg] = herm4(acc[j][1] + sbia[coA + 1], a0, a1, a2, a3, a4);
        buf[(coA + 8) * 720 + yb + xg] = herm4(acc[j][4] + sbia[coA + 8], a0, a1, a2, a3, a4);
        buf[(coA + 9) * 720 + yb + xg] = herm4(acc[j][5] + sbia[coA + 9], a0, a1, a2, a3, a4);
        if (x8 < 60) {
            buf[coA * 720 + yb + x8]       = herm4(acc[j][2] + sbia[coA],     a0, a1, a2, a3, a4);
            buf[(coA + 1) * 720 + yb + x8] = herm4(acc[j][3] + sbia[coA + 1], a0, a1, a2, a3, a4);
            buf[(coA + 8) * 720 + yb + x8] = herm4(acc[j][6] + sbia[coA + 8], a0, a1, a2, a3, a4);
            buf[(coA + 9) * 720 + yb + x8] = herm4(acc[j][7] + sbia[coA + 9], a0, a1, a2, a3, a4);
        }
    }
    __syncthreads();

    // ---- 2x2 max-pool -> g_pool1 ----
    for (int i = tid; i < 2880; i += 256) {
        int co = i / 180, pp = i % 180;
        int py = pp / 30, px = pp % 30;
        const float* bp = buf + co * 720 + (2 * py) * 60 + 2 * px;
        float m = fmaxf(fmaxf(bp[0], bp[1]), fmaxf(bp[60], bp[61]));
        g_pool1[((img * 16 + co) * 30 + band * 6 + py) * 30 + px] = m;
    }
}

// ---------------------------------------------------------------------------
// Kernel 2: conv2 via mma.sync, register-blocked (R15, proven 77us)
// ---------------------------------------------------------------------------
#define C2_SMEM 126528

__global__ void __launch_bounds__(256)
conv2_mma_kernel(const float* __restrict__ coef,
                 const float* __restrict__ w,
                 const float* __restrict__ bias) {
    extern __shared__ __align__(16) char sm[];
    __nv_bfloat16* shi  = (__nv_bfloat16*)(sm);
    __nv_bfloat16* slo  = (__nv_bfloat16*)(sm + 28800);
    __nv_bfloat16* bwh  = (__nv_bfloat16*)(sm + 57600);
    __nv_bfloat16* bwl  = (__nv_bfloat16*)(sm + 70400);
    float*         buf  = (float*)(sm + 83200);      // [co][676]
    float*         sbia = (float*)(sm + 126464);

    const int tid = threadIdx.x;
    const int img = blockIdx.x;

    const float* xim = g_pool1 + (size_t)img * 14400;
    for (int i = tid; i < 14400; i += 256) {
        int cin = i / 900, rem = i % 900;
        float v = xim[i];
        __nv_bfloat16 h = __float2bfloat16(v);
        __nv_bfloat16 l = __float2bfloat16(v - __bfloat162float(h));
        int d = rem * 16 + cin;
        shi[d] = h;
        slo[d] = l;
    }
    for (int i = tid; i < 6400; i += 256) {
        int ks = i / 256, r = i % 256, co = r / 16, cin = r % 16;
        float v = w[co * 400 + cin * 25 + ks];
        __nv_bfloat16 h = __float2bfloat16(v);
        __nv_bfloat16 l = __float2bfloat16(v - __bfloat162float(h));
        bwh[i] = h;
        bwl[i] = l;
    }
    if (tid < 16) sbia[tid] = bias[tid];
    __syncthreads();

    const float c0 = __ldg(coef + 0), c1 = __ldg(coef + 1), c2 = __ldg(coef + 2),
                c3 = __ldg(coef + 3), c4 = __ldg(coef + 4);
    const float a0 = c0 - 2.0f * c2 + 12.0f * c4;
    const float a1 = 2.0f * c1 - 12.0f * c3;
    const float a2 = 4.0f * c2 - 48.0f * c4;
    const float a3 = 8.0f * c3;
    const float a4 = 16.0f * c4;

    const int warp = tid >> 5, lane = tid & 31;
    const int g = lane >> 2, t4 = lane & 3;
    const uint32_t* ih = (const uint32_t*)shi;
    const uint32_t* il = (const uint32_t*)slo;
    const uint32_t* wh = (const uint32_t*)bwh;
    const uint32_t* wl = (const uint32_t*)bwl;

    int e0[6], e1[6];
    bool v0[6], v1[6];
    int p0a[6], p1a[6];
    #pragma unroll
    for (int j = 0; j < 6; j++) {
        int tile = warp + 8 * j;
        int p0 = tile * 16 + g;
        int p1 = p0 + 8;
        v0[j] = p0 < 676; v1[j] = p1 < 676;
        p0a[j] = p0; p1a[j] = p1;
        int q0 = v0[j] ? p0 : 675, q1 = v1[j] ? p1 : 675;
        e0[j] = (q0 / 26) * 30 + (q0 % 26);
        e1[j] = (q1 / 26) * 30 + (q1 % 26);
    }

    float acc[6][8];
    #pragma unroll
    for (int j = 0; j < 6; j++)
        #pragma unroll
        for (int k = 0; k < 8; k++) acc[j][k] = 0.0f;

    #pragma unroll 1
    for (int ks = 0; ks < 25; ks++) {
        const int off = (ks / 5) * 30 + (ks % 5);
        const int wb = ks * 128 + g * 8 + t4;
        const uint32_t bh0 = wh[wb],      bh1 = wh[wb + 4];
        const uint32_t bl0 = wl[wb],      bl1 = wl[wb + 4];
        const uint32_t ch0 = wh[wb + 64], ch1 = wh[wb + 68];
        const uint32_t cl0 = wl[wb + 64], cl1 = wl[wb + 68];

        #pragma unroll
        for (int j = 0; j < 6; j++) {
            const int r0 = (e0[j] + off) * 8 + t4;
            const int r1 = (e1[j] + off) * 8 + t4;
            uint32_t ah0 = ih[r0],     ah1 = ih[r1];
            uint32_t ah2 = ih[r0 + 4], ah3 = ih[r1 + 4];
            uint32_t al0 = il[r0],     al1 = il[r1];
            uint32_t al2 = il[r0 + 4], al3 = il[r1 + 4];

            MMA16816(acc[j][0], acc[j][1], acc[j][2], acc[j][3],
                     ah0, ah1, ah2, ah3, bh0, bh1);
            MMA16816(acc[j][0], acc[j][1], acc[j][2], acc[j][3],
                     ah0, ah1, ah2, ah3, bl0, bl1);
            MMA16816(acc[j][0], acc[j][1], acc[j][2], acc[j][3],
                     al0, al1, al2, al3, bh0, bh1);

            MMA16816(acc[j][4], acc[j][5], acc[j][6], acc[j][7],
                     ah0, ah1, ah2, ah3, ch0, ch1);
            MMA16816(acc[j][4], acc[j][5], acc[j][6], acc[j][7],
                     ah0, ah1, ah2, ah3, cl0, cl1);
            MMA16816(acc[j][4], acc[j][5], acc[j][6], acc[j][7],
                     al0, al1, al2, al3, ch0, ch1);
        }
    }

    const int coA = t4 * 2;
    #pragma unroll
    for (int j = 0; j < 6; j++) {
        if (v0[j]) {
            buf[coA * 676 + p0a[j]]       = herm4(acc[j][0] + sbia[coA],     a0, a1, a2, a3, a4);
            buf[(coA + 1) * 676 + p0a[j]] = herm4(acc[j][1] + sbia[coA + 1], a0, a1, a2, a3, a4);
            buf[(coA + 8) * 676 + p0a[j]] = herm4(acc[j][4] + sbia[coA + 8], a0, a1, a2, a3, a4);
            buf[(coA + 9) * 676 + p0a[j]] = herm4(acc[j][5] + sbia[coA + 9], a0, a1, a2, a3, a4);
        }
        if (v1[j]) {
            buf[coA * 676 + p1a[j]]       = herm4(acc[j][2] + sbia[coA],     a0, a1, a2, a3, a4);
            buf[(coA + 1) * 676 + p1a[j]] = herm4(acc[j][3] + sbia[coA + 1], a0, a1, a2, a3, a4);
            buf[(coA + 8) * 676 + p1a[j]] = herm4(acc[j][6] + sbia[coA + 8], a0, a1, a2, a3, a4);
            buf[(coA + 9) * 676 + p1a[j]] = herm4(acc[j][7] + sbia[coA + 9], a0, a1, a2, a3, a4);
        }
    }
    __syncthreads();

    for (int i = tid; i < 2704; i += 256) {
        int co = i / 169, pp = i % 169;
        int py = pp / 13, px = pp % 13;
        const float* bp = buf + co * 676 + (2 * py) * 26 + 2 * px;
        float m = fmaxf(fmaxf(bp[0], bp[1]), fmaxf(bp[26], bp[27]));
        g_pool2[((img * 16 + co) * 13 + py) * 13 + px] = m;
    }
}

// ---------------------------------------------------------------------------
// Kernel 3: FC [512,2704] @ [2704,10]^T + bias
// ---------------------------------------------------------------------------
__global__ void __launch_bounds__(128)
fc_kernel(const float* __restrict__ w,
          const float* __restrict__ bias,
          float* __restrict__ out) {
    const int img = blockIdx.x;
    const int tid = threadIdx.x;

    const float* xv = g_pool2 + (size_t)img * 2704;
    float p[10];
    #pragma unroll
    for (int o = 0; o < 10; o++) p[o] = 0.0f;

    for (int k = tid; k < 2704; k += 128) {
        float v = xv[k];
        #pragma unroll
        for (int o = 0; o < 10; o++) p[o] = fmaf(v, w[o * 2704 + k], p[o]);
    }

    __shared__ float red[4][10];
    const int lane = tid & 31, wrp = tid >> 5;
    #pragma unroll
    for (int o = 0; o < 10; o++) {
        float v = p[o];
        #pragma unroll
        for (int s = 16; s > 0; s >>= 1)
            v += __shfl_down_sync(0xffffffffu, v, s);
        if (lane == 0) red[wrp][o] = v;
    }
    __syncthreads();
    if (tid < 10)
        out[img * 10 + tid] =
            red[0][tid] + red[1][tid] + red[2][tid] + red[3][tid] + bias[tid];
}

// ---------------------------------------------------------------------------
extern "C" void kernel_launch(void* const* d_in, const int* in_sizes, int n_in,
                              void* d_out, int out_size) {
    const float* x       = (const float*)d_in[0];
    const float* coef    = (const float*)d_in[1];
    const float* conv1_w = (const float*)d_in[2];
    const float* conv1_b = (const float*)d_in[3];
    const float* conv2_w = (const float*)d_in[4];
    const float* conv2_b = (const float*)d_in[5];
    const float* fc1_w   = (const float*)d_in[6];
    const float* fc1_b   = (const float*)d_in[7];
    float* out = (float*)d_out;

    cudaFuncSetAttribute(conv1_mma_kernel,
                         cudaFuncAttributeMaxDynamicSharedMemorySize, C1_SMEM);
    cudaFuncSetAttribute(conv2_mma_kernel,
                         cudaFuncAttributeMaxDynamicSharedMemorySize, C2_SMEM);

    conv1_mma_kernel<<<B_IMG * 5, 256, C1_SMEM>>>(x, coef, conv1_w, conv1_b);
    conv2_mma_kernel<<<B_IMG, 256, C2_SMEM>>>(coef, conv2_w, conv2_b);
    fc_kernel<<<B_IMG, 128>>>(fc1_w, fc1_b, out);
}